// round 1
// baseline (speedup 1.0000x reference)
#include <cuda_runtime.h>
#include <math.h>

#define NS 128      // num_steps
#define NU 128      // upsample_steps
#define NT 256      // total samples
#define HD 64       // hidden dim
#define BOUND 2.0f

// ---------------------------------------------------------------------------
// Inclusive scans over shared arrays, 128 threads, n <= 256 (Hillis-Steele).
// Caller must __syncthreads() before calling.
// ---------------------------------------------------------------------------
__device__ __forceinline__ void scan_prod(float* s, int n, int tid) {
    for (int off = 1; off < n; off <<= 1) {
        int i0 = tid, i1 = tid + 128;
        float n0 = 0.f, n1 = 0.f;
        bool u0 = (i0 < n), u1 = (i1 < n);
        if (u0) { float c = s[i0]; n0 = (i0 >= off) ? c * s[i0 - off] : c; }
        if (u1) { float c = s[i1]; n1 = (i1 >= off) ? c * s[i1 - off] : c; }
        __syncthreads();
        if (u0) s[i0] = n0;
        if (u1) s[i1] = n1;
        __syncthreads();
    }
}

__device__ __forceinline__ void scan_sum(float* s, int n, int tid) {
    for (int off = 1; off < n; off <<= 1) {
        int i0 = tid;
        float n0 = 0.f;
        bool u0 = (i0 < n);
        if (u0) { float c = s[i0]; n0 = (i0 >= off) ? c + s[i0 - off] : c; }
        __syncthreads();
        if (u0) s[i0] = n0;
        __syncthreads();
    }
}

// NaN-propagating clip (jnp.clip semantics: NaN stays NaN)
__device__ __forceinline__ float clipf(float x, float lo, float hi) {
    return x < lo ? lo : (x > hi ? hi : x);
}

// ---------------------------------------------------------------------------
// Tiny MLP:  h = relu(p@W1+b1); h2 = relu(h@W2+b2);
//            sigma = softplus(h2@Wsig); rgb = sigmoid([h2,d]@Wrgb + brgb)
// Weights in shared memory; W2 stored transposed [j][k] for float4 reads.
// ---------------------------------------------------------------------------
__device__ __forceinline__ void mlp_eval(
    const float* __restrict__ sW1, const float* __restrict__ sB1,
    const float* __restrict__ sW2T, const float* __restrict__ sB2,
    const float* __restrict__ sWsig, const float* __restrict__ sWrgb,
    const float* __restrict__ sBrgb,
    float px, float py, float pz, float dx, float dy, float dz,
    float& sigma, float& r0o, float& r1o, float& r2o)
{
    float h[HD];
#pragma unroll
    for (int j = 0; j < HD; j++) {
        float v = fmaf(px, sW1[j], fmaf(py, sW1[HD + j], fmaf(pz, sW1[2 * HD + j], sB1[j])));
        h[j] = fmaxf(v, 0.f);
    }
    float sa = 0.f;
    float r0 = fmaf(dx, sWrgb[64 * 3 + 0], fmaf(dy, sWrgb[65 * 3 + 0], fmaf(dz, sWrgb[66 * 3 + 0], sBrgb[0])));
    float r1 = fmaf(dx, sWrgb[64 * 3 + 1], fmaf(dy, sWrgb[65 * 3 + 1], fmaf(dz, sWrgb[66 * 3 + 1], sBrgb[1])));
    float r2 = fmaf(dx, sWrgb[64 * 3 + 2], fmaf(dy, sWrgb[65 * 3 + 2], fmaf(dz, sWrgb[66 * 3 + 2], sBrgb[2])));

#pragma unroll 1
    for (int j = 0; j < HD; j += 4) {
        float a0 = sB2[j], a1 = sB2[j + 1], a2 = sB2[j + 2], a3 = sB2[j + 3];
        const float4* w0 = (const float4*)(sW2T + (j + 0) * HD);
        const float4* w1 = (const float4*)(sW2T + (j + 1) * HD);
        const float4* w2 = (const float4*)(sW2T + (j + 2) * HD);
        const float4* w3 = (const float4*)(sW2T + (j + 3) * HD);
#pragma unroll
        for (int q = 0; q < HD / 4; q++) {
            float4 x0 = w0[q], x1 = w1[q], x2 = w2[q], x3 = w3[q];
            float h0 = h[4 * q], h1 = h[4 * q + 1], h2v = h[4 * q + 2], h3 = h[4 * q + 3];
            a0 = fmaf(h0, x0.x, a0); a0 = fmaf(h1, x0.y, a0); a0 = fmaf(h2v, x0.z, a0); a0 = fmaf(h3, x0.w, a0);
            a1 = fmaf(h0, x1.x, a1); a1 = fmaf(h1, x1.y, a1); a1 = fmaf(h2v, x1.z, a1); a1 = fmaf(h3, x1.w, a1);
            a2 = fmaf(h0, x2.x, a2); a2 = fmaf(h1, x2.y, a2); a2 = fmaf(h2v, x2.z, a2); a2 = fmaf(h3, x2.w, a2);
            a3 = fmaf(h0, x3.x, a3); a3 = fmaf(h1, x3.y, a3); a3 = fmaf(h2v, x3.z, a3); a3 = fmaf(h3, x3.w, a3);
        }
        a0 = fmaxf(a0, 0.f); a1 = fmaxf(a1, 0.f); a2 = fmaxf(a2, 0.f); a3 = fmaxf(a3, 0.f);
        sa = fmaf(a0, sWsig[j], sa); sa = fmaf(a1, sWsig[j + 1], sa);
        sa = fmaf(a2, sWsig[j + 2], sa); sa = fmaf(a3, sWsig[j + 3], sa);
        r0 = fmaf(a0, sWrgb[(j + 0) * 3 + 0], r0); r0 = fmaf(a1, sWrgb[(j + 1) * 3 + 0], r0);
        r0 = fmaf(a2, sWrgb[(j + 2) * 3 + 0], r0); r0 = fmaf(a3, sWrgb[(j + 3) * 3 + 0], r0);
        r1 = fmaf(a0, sWrgb[(j + 0) * 3 + 1], r1); r1 = fmaf(a1, sWrgb[(j + 1) * 3 + 1], r1);
        r1 = fmaf(a2, sWrgb[(j + 2) * 3 + 1], r1); r1 = fmaf(a3, sWrgb[(j + 3) * 3 + 1], r1);
        r2 = fmaf(a0, sWrgb[(j + 0) * 3 + 2], r2); r2 = fmaf(a1, sWrgb[(j + 1) * 3 + 2], r2);
        r2 = fmaf(a2, sWrgb[(j + 2) * 3 + 2], r2); r2 = fmaf(a3, sWrgb[(j + 3) * 3 + 2], r2);
    }
    // softplus (stable): max(x,0) + log1p(exp(-|x|))
    sigma = fmaxf(sa, 0.f) + log1pf(expf(-fabsf(sa)));
    r0o = 1.f / (1.f + expf(-r0));
    r1o = 1.f / (1.f + expf(-r1));
    r2o = 1.f / (1.f + expf(-r2));
}

// ---------------------------------------------------------------------------
// One CTA per ray. 128 threads: one sample per thread per pass.
// ---------------------------------------------------------------------------
__global__ void __launch_bounds__(128)
nerf_render_kernel(const float* __restrict__ rays_o, const float* __restrict__ rays_d,
                   const float* __restrict__ W1, const float* __restrict__ b1,
                   const float* __restrict__ W2, const float* __restrict__ b2,
                   const float* __restrict__ Wsig, const float* __restrict__ Wrgb,
                   const float* __restrict__ brgb,
                   float* __restrict__ out, int nrays)
{
    __shared__ float sW1[3 * HD], sB1[HD], sW2T[HD * HD], sB2[HD], sWsig[HD];
    __shared__ float sWrgb[67 * 3], sBrgb[3];
    __shared__ float sZ[NT], sSig[NT], sRGB[NT * 3];
    __shared__ float sA[NT];      // alphas / weights
    __shared__ float sBuf[NT];    // scan buffer (transmittance / cdf)
    __shared__ float sC[NS];      // z_mid bins
    __shared__ float sRed[4 * 5]; // cross-warp reduction

    const int tid = threadIdx.x;
    const int ray = blockIdx.x;
    if (ray >= nrays) return;

    // --- cooperative weight load (W2 transposed) ---
    for (int i = tid; i < 3 * HD; i += 128) sW1[i] = W1[i];
    if (tid < HD) { sB1[tid] = b1[tid]; sB2[tid] = b2[tid]; sWsig[tid] = Wsig[tid]; }
    for (int i = tid; i < HD * HD; i += 128) {
        int k = i / HD, j = i % HD;
        sW2T[j * HD + k] = W2[i];
    }
    for (int i = tid; i < 67 * 3; i += 128) sWrgb[i] = Wrgb[i];
    if (tid < 3) sBrgb[tid] = brgb[tid];

    // --- per-ray setup (redundant per thread, cheap) ---
    const float ox = rays_o[ray * 3 + 0], oy = rays_o[ray * 3 + 1], oz = rays_o[ray * 3 + 2];
    const float dx = rays_d[ray * 3 + 0], dy = rays_d[ray * 3 + 1], dz = rays_d[ray * 3 + 2];

    float near = -3.0e38f, far = 3.0e38f;
    {
        float o3[3] = {ox, oy, oz}, d3[3] = {dx, dy, dz};
#pragma unroll
        for (int c = 0; c < 3; c++) {
            float den = d3[c] + 1e-15f;
            float tmn = (-BOUND - o3[c]) / den;
            float tmx = ( BOUND - o3[c]) / den;
            near = fmaxf(near, fminf(tmn, tmx));
            far  = fminf(far,  fmaxf(tmn, tmx));
        }
        if (far < near) { near = 1e9f; far = 1e9f; }
        near = fmaxf(near, 0.05f);
    }
    const float span = far - near;
    const float sample_dist = span / (float)NS;

    __syncthreads();

    // ========== Phase A: coarse samples ==========
    {
        float z = near + span * ((float)tid * (1.f / 127.f));
        float px = clipf(fmaf(dx, z, ox), -BOUND, BOUND);
        float py = clipf(fmaf(dy, z, oy), -BOUND, BOUND);
        float pz = clipf(fmaf(dz, z, oz), -BOUND, BOUND);
        float sg, r0, r1, r2;
        mlp_eval(sW1, sB1, sW2T, sB2, sWsig, sWrgb, sBrgb, px, py, pz, dx, dy, dz, sg, r0, r1, r2);
        sZ[tid] = z; sSig[tid] = sg;
        sRGB[tid * 3 + 0] = r0; sRGB[tid * 3 + 1] = r1; sRGB[tid * 3 + 2] = r2;
    }
    __syncthreads();

    // ========== Phase B: coarse weights -> pdf -> resample ==========
    {
        float delta = (tid < NS - 1) ? (sZ[tid + 1] - sZ[tid]) : sample_dist;
        float alpha = 1.f - expf(-delta * sSig[tid]);
        sA[tid]   = alpha;
        sBuf[tid] = 1.f - alpha + 1e-15f;
        if (tid < NS - 1) sC[tid] = sZ[tid] + 0.5f * delta;  // z_mid bins [127]
    }
    __syncthreads();
    scan_prod(sBuf, NS, tid);                 // inclusive transmittance products
    float w_coarse = sA[tid] * (tid == 0 ? 1.f : sBuf[tid - 1]);
    __syncthreads();
    sA[tid] = w_coarse;                       // weights [128]
    __syncthreads();
    // pdf raw = weights[1..126] + 1e-5  (126 entries)
    if (tid < 126) sBuf[tid] = sA[tid + 1] + 1e-5f;
    __syncthreads();
    scan_sum(sBuf, 126, tid);                 // inclusive cumsum
    const float Ssum = sBuf[125];

    float new_z;
    {
        // u = linspace(0.5/128, 1-0.5/128, 128)
        float u = 0.00390625f + (float)tid * 0.0078125f;
        // searchsorted(cdf, u, side='right'); cdf[i] = (i==0 ? 0 : sBuf[i-1]/Ssum), len 127
        int lo = 0, hi = 127;
        while (lo < hi) {
            int m = (lo + hi) >> 1;
            float c = (m == 0) ? 0.f : sBuf[m - 1] / Ssum;
            if (c <= u) lo = m + 1; else hi = m;
        }
        int ind = lo;
        int below = max(ind - 1, 0);
        int above = min(ind, 126);
        float cb = (below == 0) ? 0.f : sBuf[below - 1] / Ssum;
        float ca = (above == 0) ? 0.f : sBuf[above - 1] / Ssum;
        float bb = sC[below], ba = sC[above];
        float den = ca - cb;
        if (den < 1e-5f) den = 1.f;
        float t = (u - cb) / den;
        new_z = bb + t * (ba - bb);
    }

    // ========== Phase C: fine samples ==========
    {
        float z = new_z;
        float px = clipf(fmaf(dx, z, ox), -BOUND, BOUND);
        float py = clipf(fmaf(dy, z, oy), -BOUND, BOUND);
        float pz = clipf(fmaf(dz, z, oz), -BOUND, BOUND);
        float sg, r0, r1, r2;
        mlp_eval(sW1, sB1, sW2T, sB2, sWsig, sWrgb, sBrgb, px, py, pz, dx, dy, dz, sg, r0, r1, r2);
        sZ[NS + tid] = z; sSig[NS + tid] = sg;
        sRGB[(NS + tid) * 3 + 0] = r0; sRGB[(NS + tid) * 3 + 1] = r1; sRGB[(NS + tid) * 3 + 2] = r2;
    }
    __syncthreads();

    // ========== Phase D: stable merge of two sorted runs (== stable argsort) ==========
    {
        float zA = sZ[tid], zB = sZ[NS + tid];
        // posA = tid + |{B < zA}|
        int lo = 0, hi = NS;
        while (lo < hi) { int m = (lo + hi) >> 1; if (sZ[NS + m] < zA) lo = m + 1; else hi = m; }
        int posA = tid + lo;
        // posB = tid + |{A <= zB}|
        lo = 0; hi = NS;
        while (lo < hi) { int m = (lo + hi) >> 1; if (sZ[m] <= zB) lo = m + 1; else hi = m; }
        int posB = tid + lo;

        float sgA = sSig[tid], sgB = sSig[NS + tid];
        float a0 = sRGB[tid * 3 + 0], a1 = sRGB[tid * 3 + 1], a2 = sRGB[tid * 3 + 2];
        float b0 = sRGB[(NS + tid) * 3 + 0], b1v = sRGB[(NS + tid) * 3 + 1], b2v = sRGB[(NS + tid) * 3 + 2];
        __syncthreads();
        sZ[posA] = zA; sSig[posA] = sgA;
        sRGB[posA * 3 + 0] = a0; sRGB[posA * 3 + 1] = a1; sRGB[posA * 3 + 2] = a2;
        sZ[posB] = zB; sSig[posB] = sgB;
        sRGB[posB * 3 + 0] = b0; sRGB[posB * 3 + 1] = b1v; sRGB[posB * 3 + 2] = b2v;
        __syncthreads();
    }

    // ========== Phase E: final composite over 256 sorted samples ==========
    {
#pragma unroll
        for (int r = 0; r < 2; r++) {
            int i = tid + r * 128;
            float delta = (i < NT - 1) ? (sZ[i + 1] - sZ[i]) : sample_dist;
            float alpha = 1.f - expf(-delta * sSig[i]);
            sA[i]   = alpha;
            sBuf[i] = 1.f - alpha + 1e-15f;
        }
        __syncthreads();
        scan_prod(sBuf, NT, tid);

        float wsum = 0.f, dsum = 0.f, rs0 = 0.f, rs1 = 0.f, rs2 = 0.f;
#pragma unroll
        for (int r = 0; r < 2; r++) {
            int i = tid + r * 128;
            float w = sA[i] * (i == 0 ? 1.f : sBuf[i - 1]);
            float v = clipf((sZ[i] - near) / span, 0.f, 1.f);   // NaN-propagating
            wsum += w;
            dsum += w * v;
            rs0 = fmaf(w, sRGB[i * 3 + 0], rs0);
            rs1 = fmaf(w, sRGB[i * 3 + 1], rs1);
            rs2 = fmaf(w, sRGB[i * 3 + 2], rs2);
        }
        // warp reduce 5 values
#pragma unroll
        for (int o = 16; o > 0; o >>= 1) {
            wsum += __shfl_down_sync(0xffffffffu, wsum, o);
            dsum += __shfl_down_sync(0xffffffffu, dsum, o);
            rs0  += __shfl_down_sync(0xffffffffu, rs0, o);
            rs1  += __shfl_down_sync(0xffffffffu, rs1, o);
            rs2  += __shfl_down_sync(0xffffffffu, rs2, o);
        }
        int warp = tid >> 5, lane = tid & 31;
        if (lane == 0) {
            sRed[warp * 5 + 0] = wsum; sRed[warp * 5 + 1] = dsum;
            sRed[warp * 5 + 2] = rs0;  sRed[warp * 5 + 3] = rs1; sRed[warp * 5 + 4] = rs2;
        }
        __syncthreads();
        if (tid == 0) {
            float W = 0, D = 0, R0 = 0, R1 = 0, R2 = 0;
#pragma unroll
            for (int w2 = 0; w2 < 4; w2++) {
                W += sRed[w2 * 5 + 0]; D += sRed[w2 * 5 + 1];
                R0 += sRed[w2 * 5 + 2]; R1 += sRed[w2 * 5 + 3]; R2 += sRed[w2 * 5 + 4];
            }
            float bg = 1.f - W;  // bg_color = 1
            out[ray] = D;
            out[nrays + ray * 3 + 0] = R0 + bg;
            out[nrays + ray * 3 + 1] = R1 + bg;
            out[nrays + ray * 3 + 2] = R2 + bg;
        }
    }
}

extern "C" void kernel_launch(void* const* d_in, const int* in_sizes, int n_in,
                              void* d_out, int out_size) {
    const float* rays_o = (const float*)d_in[0];
    const float* rays_d = (const float*)d_in[1];
    const float* W1   = (const float*)d_in[2];
    const float* b1   = (const float*)d_in[3];
    const float* W2   = (const float*)d_in[4];
    const float* b2   = (const float*)d_in[5];
    const float* Wsig = (const float*)d_in[6];
    const float* Wrgb = (const float*)d_in[7];
    const float* brgb = (const float*)d_in[8];
    float* out = (float*)d_out;

    int nrays = in_sizes[0] / 3;   // B*N
    nerf_render_kernel<<<nrays, 128>>>(rays_o, rays_d, W1, b1, W2, b2, Wsig, Wrgb, brgb,
                                       out, nrays);
}

// round 2
// speedup vs baseline: 1.5842x; 1.5842x over previous
#include <cuda_runtime.h>
#include <math.h>

#define NS 128
#define NT 256
#define HD 64
#define BOUND 2.0f

// ---- dynamic shared memory layout (float offsets) ----
#define O_W1   0          // 192
#define O_B1   192        // 64
#define O_B2   256        // 64
#define O_WSIG 320        // 64
#define O_WRGB 384        // 201 (+3 pad)
#define O_BRGB 588        // 3 (+1 pad)
#define O_W2   592        // 4096 (original [k][j] layout)
#define O_Z    4688       // 256
#define O_SIG  4944       // 256
#define O_RGB  5200       // 768
#define O_A    5968       // 256
#define O_BUF  6224       // 256
#define O_C    6480       // 128
#define O_RED  6608       // 20 (+4 pad)
#define O_HT   6632       // 8192  (hT[64][128], unioned with sPart[128][33])
#define SMEM_FLOATS (6632 + 8192)

// packed dual-FMA (sm_103a f32x2 path — double-rate fp32)
__device__ __forceinline__ float2 ffma2(float2 a, float2 b, float2 c) {
    float2 d;
    asm("fma.rn.f32x2 %0, %1, %2, %3;"
        : "=l"(reinterpret_cast<unsigned long long&>(d))
        : "l"(reinterpret_cast<unsigned long long&>(a)),
          "l"(reinterpret_cast<unsigned long long&>(b)),
          "l"(reinterpret_cast<unsigned long long&>(c)));
    return d;
}

// NaN-propagating clip (jnp.clip semantics)
__device__ __forceinline__ float clipf(float x, float lo, float hi) {
    return x < lo ? lo : (x > hi ? hi : x);
}

// inclusive scans, 128 threads, n <= 256
__device__ __forceinline__ void scan_prod(float* s, int n, int tid) {
    for (int off = 1; off < n; off <<= 1) {
        int i0 = tid, i1 = tid + 128;
        float n0 = 0.f, n1 = 0.f;
        bool u0 = (i0 < n), u1 = (i1 < n);
        if (u0) { float c = s[i0]; n0 = (i0 >= off) ? c * s[i0 - off] : c; }
        if (u1) { float c = s[i1]; n1 = (i1 >= off) ? c * s[i1 - off] : c; }
        __syncthreads();
        if (u0) s[i0] = n0;
        if (u1) s[i1] = n1;
        __syncthreads();
    }
}
__device__ __forceinline__ void scan_sum(float* s, int n, int tid) {
    for (int off = 1; off < n; off <<= 1) {
        float n0 = 0.f;
        bool u0 = (tid < n);
        if (u0) { float c = s[tid]; n0 = (tid >= off) ? c + s[tid - off] : c; }
        __syncthreads();
        if (u0) s[tid] = n0;
        __syncthreads();
    }
}

// ---------------------------------------------------------------------------
// One "field" pass for 128 samples: per-thread W1 -> staged hT -> cooperative
// 128x64x64 register-blocked GEMM (8x8 tiles, FFMA2) -> heads via partial
// reduction. Writes sSig/sRGB at [outBase + tid].
// ---------------------------------------------------------------------------
__device__ __forceinline__ void field_pass(
    float* sm, int tid, float z,
    float ox, float oy, float oz, float dx, float dy, float dz,
    int outBase)
{
    // ---- layer 1 (3 -> 64), packed, store transposed hT[k][m] ----
    {
        float px = clipf(fmaf(dx, z, ox), -BOUND, BOUND);
        float py = clipf(fmaf(dy, z, oy), -BOUND, BOUND);
        float pz = clipf(fmaf(dz, z, oz), -BOUND, BOUND);
        float2 PX = make_float2(px, px), PY = make_float2(py, py), PZ = make_float2(pz, pz);
        const float2* w1p = (const float2*)(sm + O_W1);
        const float2* b1p = (const float2*)(sm + O_B1);
        float* hT = sm + O_HT;
#pragma unroll
        for (int jp = 0; jp < 32; jp++) {
            float2 v = ffma2(PX, w1p[jp], ffma2(PY, w1p[32 + jp], ffma2(PZ, w1p[64 + jp], b1p[jp])));
            hT[(2 * jp) * 128 + tid]     = fmaxf(v.x, 0.f);
            hT[(2 * jp + 1) * 128 + tid] = fmaxf(v.y, 0.f);
        }
    }
    __syncthreads();

    // ---- GEMM: h2[128 samples][64] = hT^T @ W2  (8x8 per thread) ----
    const int mt = tid & 15, nt = tid >> 4;
    const int m0 = mt * 8, j0 = nt * 8;
    float2 acc[8][4];
    {
        const float2* b2p = (const float2*)(sm + O_B2);
        float2 bb0 = b2p[j0 / 2 + 0], bb1 = b2p[j0 / 2 + 1];
        float2 bb2 = b2p[j0 / 2 + 2], bb3 = b2p[j0 / 2 + 3];
#pragma unroll
        for (int m = 0; m < 8; m++) {
            acc[m][0] = bb0; acc[m][1] = bb1; acc[m][2] = bb2; acc[m][3] = bb3;
        }
        const float* hT = sm + O_HT;
        const float* W2 = sm + O_W2;
#pragma unroll 4
        for (int k = 0; k < 64; k++) {
            float4 a0 = *(const float4*)(hT + k * 128 + m0);
            float4 a1 = *(const float4*)(hT + k * 128 + m0 + 4);
            float4 w0 = *(const float4*)(W2 + k * 64 + j0);
            float4 w1 = *(const float4*)(W2 + k * 64 + j0 + 4);
            float2 wp0 = make_float2(w0.x, w0.y), wp1 = make_float2(w0.z, w0.w);
            float2 wp2 = make_float2(w1.x, w1.y), wp3 = make_float2(w1.z, w1.w);
            float am[8] = {a0.x, a0.y, a0.z, a0.w, a1.x, a1.y, a1.z, a1.w};
#pragma unroll
            for (int m = 0; m < 8; m++) {
                float2 hs = make_float2(am[m], am[m]);
                acc[m][0] = ffma2(hs, wp0, acc[m][0]);
                acc[m][1] = ffma2(hs, wp1, acc[m][1]);
                acc[m][2] = ffma2(hs, wp2, acc[m][2]);
                acc[m][3] = ffma2(hs, wp3, acc[m][3]);
            }
        }
    }
    __syncthreads();   // all GEMM reads of hT done before sPart overwrites it

    // ---- relu + head partials (this thread's 8 j-cols), to sPart[m][nt*4+c] ----
    {
        float wsig[8], wr0[8], wr1[8], wr2[8];
#pragma unroll
        for (int jj = 0; jj < 8; jj++) {
            wsig[jj] = sm[O_WSIG + j0 + jj];
            wr0[jj] = sm[O_WRGB + (j0 + jj) * 3 + 0];
            wr1[jj] = sm[O_WRGB + (j0 + jj) * 3 + 1];
            wr2[jj] = sm[O_WRGB + (j0 + jj) * 3 + 2];
        }
        float* sPart = sm + O_HT;
#pragma unroll
        for (int m = 0; m < 8; m++) {
            float h2v[8];
            h2v[0] = fmaxf(acc[m][0].x, 0.f); h2v[1] = fmaxf(acc[m][0].y, 0.f);
            h2v[2] = fmaxf(acc[m][1].x, 0.f); h2v[3] = fmaxf(acc[m][1].y, 0.f);
            h2v[4] = fmaxf(acc[m][2].x, 0.f); h2v[5] = fmaxf(acc[m][2].y, 0.f);
            h2v[6] = fmaxf(acc[m][3].x, 0.f); h2v[7] = fmaxf(acc[m][3].y, 0.f);
            float sg = 0.f, r0 = 0.f, r1 = 0.f, r2 = 0.f;
#pragma unroll
            for (int jj = 0; jj < 8; jj++) {
                sg = fmaf(h2v[jj], wsig[jj], sg);
                r0 = fmaf(h2v[jj], wr0[jj], r0);
                r1 = fmaf(h2v[jj], wr1[jj], r1);
                r2 = fmaf(h2v[jj], wr2[jj], r2);
            }
            int base = (m0 + m) * 33 + nt * 4;
            sPart[base + 0] = sg; sPart[base + 1] = r0;
            sPart[base + 2] = r1; sPart[base + 3] = r2;
        }
    }
    __syncthreads();

    // ---- per-sample finalize: reduce 8 partials, dir terms, activations ----
    {
        const float* sPart = sm + O_HT;
        float sg = 0.f, r0 = 0.f, r1 = 0.f, r2 = 0.f;
#pragma unroll
        for (int g = 0; g < 8; g++) {
            int base = tid * 33 + g * 4;
            sg += sPart[base + 0]; r0 += sPart[base + 1];
            r1 += sPart[base + 2]; r2 += sPart[base + 3];
        }
        r0 += fmaf(dx, sm[O_WRGB + 64 * 3 + 0], fmaf(dy, sm[O_WRGB + 65 * 3 + 0], fmaf(dz, sm[O_WRGB + 66 * 3 + 0], sm[O_BRGB + 0])));
        r1 += fmaf(dx, sm[O_WRGB + 64 * 3 + 1], fmaf(dy, sm[O_WRGB + 65 * 3 + 1], fmaf(dz, sm[O_WRGB + 66 * 3 + 1], sm[O_BRGB + 1])));
        r2 += fmaf(dx, sm[O_WRGB + 64 * 3 + 2], fmaf(dy, sm[O_WRGB + 65 * 3 + 2], fmaf(dz, sm[O_WRGB + 66 * 3 + 2], sm[O_BRGB + 2])));
        float sigma = fmaxf(sg, 0.f) + log1pf(expf(-fabsf(sg)));   // stable softplus
        sm[O_SIG + outBase + tid] = sigma;
        sm[O_RGB + (outBase + tid) * 3 + 0] = 1.f / (1.f + expf(-r0));
        sm[O_RGB + (outBase + tid) * 3 + 1] = 1.f / (1.f + expf(-r1));
        sm[O_RGB + (outBase + tid) * 3 + 2] = 1.f / (1.f + expf(-r2));
    }
}

// ---------------------------------------------------------------------------
__global__ void __launch_bounds__(128)
nerf_render_kernel(const float* __restrict__ rays_o, const float* __restrict__ rays_d,
                   const float* __restrict__ W1, const float* __restrict__ b1,
                   const float* __restrict__ W2, const float* __restrict__ b2,
                   const float* __restrict__ Wsig, const float* __restrict__ Wrgb,
                   const float* __restrict__ brgb,
                   float* __restrict__ out, int nrays)
{
    extern __shared__ float sm[];
    const int tid = threadIdx.x;
    const int ray = blockIdx.x;

    // ---- cooperative weight load (W2 kept in original [k][j] layout) ----
    for (int i = tid; i < 192; i += 128) sm[O_W1 + i] = W1[i];
    if (tid < 64) { sm[O_B1 + tid] = b1[tid]; sm[O_B2 + tid] = b2[tid]; sm[O_WSIG + tid] = Wsig[tid]; }
    for (int i = tid; i < 4096; i += 128) sm[O_W2 + i] = W2[i];
    for (int i = tid; i < 201; i += 128) sm[O_WRGB + i] = Wrgb[i];
    if (tid < 3) sm[O_BRGB + tid] = brgb[tid];

    // ---- per-ray setup ----
    const float ox = rays_o[ray * 3 + 0], oy = rays_o[ray * 3 + 1], oz = rays_o[ray * 3 + 2];
    const float dx = rays_d[ray * 3 + 0], dy = rays_d[ray * 3 + 1], dz = rays_d[ray * 3 + 2];

    float near = -3.0e38f, far = 3.0e38f;
    {
        float o3[3] = {ox, oy, oz}, d3[3] = {dx, dy, dz};
#pragma unroll
        for (int c = 0; c < 3; c++) {
            float den = d3[c] + 1e-15f;
            float tmn = (-BOUND - o3[c]) / den;
            float tmx = ( BOUND - o3[c]) / den;
            near = fmaxf(near, fminf(tmn, tmx));
            far  = fminf(far,  fmaxf(tmn, tmx));
        }
        if (far < near) { near = 1e9f; far = 1e9f; }
        near = fmaxf(near, 0.05f);
    }
    const float span = far - near;
    const float sample_dist = span / (float)NS;

    float* sZ   = sm + O_Z;
    float* sSig = sm + O_SIG;
    float* sRGB = sm + O_RGB;
    float* sA   = sm + O_A;
    float* sBuf = sm + O_BUF;
    float* sC   = sm + O_C;
    float* sRed = sm + O_RED;

    __syncthreads();

    // ========== Phase A: coarse ==========
    float zc = near + span * ((float)tid * (1.f / 127.f));
    sZ[tid] = zc;
    field_pass(sm, tid, zc, ox, oy, oz, dx, dy, dz, 0);
    __syncthreads();

    // ========== Phase B: weights -> pdf -> resample ==========
    {
        float delta = (tid < NS - 1) ? (sZ[tid + 1] - sZ[tid]) : sample_dist;
        float alpha = 1.f - expf(-delta * sSig[tid]);
        sA[tid]   = alpha;
        sBuf[tid] = 1.f - alpha + 1e-15f;
        if (tid < NS - 1) sC[tid] = sZ[tid] + 0.5f * delta;
    }
    __syncthreads();
    scan_prod(sBuf, NS, tid);
    float w_coarse = sA[tid] * (tid == 0 ? 1.f : sBuf[tid - 1]);
    __syncthreads();
    sA[tid] = w_coarse;
    __syncthreads();
    if (tid < 126) sBuf[tid] = sA[tid + 1] + 1e-5f;
    __syncthreads();
    scan_sum(sBuf, 126, tid);
    const float Ssum = sBuf[125];

    float new_z;
    {
        float u = 0.00390625f + (float)tid * 0.0078125f;
        int lo = 0, hi = 127;
        while (lo < hi) {
            int m = (lo + hi) >> 1;
            float c = (m == 0) ? 0.f : sBuf[m - 1] / Ssum;
            if (c <= u) lo = m + 1; else hi = m;
        }
        int ind = lo;
        int below = max(ind - 1, 0);
        int above = min(ind, 126);
        float cb = (below == 0) ? 0.f : sBuf[below - 1] / Ssum;
        float ca = (above == 0) ? 0.f : sBuf[above - 1] / Ssum;
        float bb = sC[below], ba = sC[above];
        float den = ca - cb;
        if (den < 1e-5f) den = 1.f;
        new_z = bb + ((u - cb) / den) * (ba - bb);
    }
    __syncthreads();

    // ========== Phase C: fine ==========
    sZ[NS + tid] = new_z;
    field_pass(sm, tid, new_z, ox, oy, oz, dx, dy, dz, NS);
    __syncthreads();

    // ========== Phase D: stable merge of two sorted runs ==========
    {
        float zA = sZ[tid], zB = sZ[NS + tid];
        int lo = 0, hi = NS;
        while (lo < hi) { int m = (lo + hi) >> 1; if (sZ[NS + m] < zA) lo = m + 1; else hi = m; }
        int posA = tid + lo;
        lo = 0; hi = NS;
        while (lo < hi) { int m = (lo + hi) >> 1; if (sZ[m] <= zB) lo = m + 1; else hi = m; }
        int posB = tid + lo;

        float sgA = sSig[tid], sgB = sSig[NS + tid];
        float a0 = sRGB[tid * 3 + 0], a1 = sRGB[tid * 3 + 1], a2 = sRGB[tid * 3 + 2];
        float b0 = sRGB[(NS + tid) * 3 + 0], b1v = sRGB[(NS + tid) * 3 + 1], b2v = sRGB[(NS + tid) * 3 + 2];
        __syncthreads();
        sZ[posA] = zA; sSig[posA] = sgA;
        sRGB[posA * 3 + 0] = a0; sRGB[posA * 3 + 1] = a1; sRGB[posA * 3 + 2] = a2;
        sZ[posB] = zB; sSig[posB] = sgB;
        sRGB[posB * 3 + 0] = b0; sRGB[posB * 3 + 1] = b1v; sRGB[posB * 3 + 2] = b2v;
        __syncthreads();
    }

    // ========== Phase E: final composite over 256 sorted samples ==========
    {
#pragma unroll
        for (int r = 0; r < 2; r++) {
            int i = tid + r * 128;
            float delta = (i < NT - 1) ? (sZ[i + 1] - sZ[i]) : sample_dist;
            float alpha = 1.f - expf(-delta * sSig[i]);
            sA[i]   = alpha;
            sBuf[i] = 1.f - alpha + 1e-15f;
        }
        __syncthreads();
        scan_prod(sBuf, NT, tid);

        float wsum = 0.f, dsum = 0.f, rs0 = 0.f, rs1 = 0.f, rs2 = 0.f;
#pragma unroll
        for (int r = 0; r < 2; r++) {
            int i = tid + r * 128;
            float w = sA[i] * (i == 0 ? 1.f : sBuf[i - 1]);
            float v = clipf((sZ[i] - near) / span, 0.f, 1.f);   // NaN-propagating
            wsum += w;
            dsum += w * v;
            rs0 = fmaf(w, sRGB[i * 3 + 0], rs0);
            rs1 = fmaf(w, sRGB[i * 3 + 1], rs1);
            rs2 = fmaf(w, sRGB[i * 3 + 2], rs2);
        }
#pragma unroll
        for (int o = 16; o > 0; o >>= 1) {
            wsum += __shfl_down_sync(0xffffffffu, wsum, o);
            dsum += __shfl_down_sync(0xffffffffu, dsum, o);
            rs0  += __shfl_down_sync(0xffffffffu, rs0, o);
            rs1  += __shfl_down_sync(0xffffffffu, rs1, o);
            rs2  += __shfl_down_sync(0xffffffffu, rs2, o);
        }
        int warp = tid >> 5, lane = tid & 31;
        if (lane == 0) {
            sRed[warp * 5 + 0] = wsum; sRed[warp * 5 + 1] = dsum;
            sRed[warp * 5 + 2] = rs0;  sRed[warp * 5 + 3] = rs1; sRed[warp * 5 + 4] = rs2;
        }
        __syncthreads();
        if (tid == 0) {
            float W = 0, D = 0, R0 = 0, R1 = 0, R2 = 0;
#pragma unroll
            for (int w2 = 0; w2 < 4; w2++) {
                W += sRed[w2 * 5 + 0]; D += sRed[w2 * 5 + 1];
                R0 += sRed[w2 * 5 + 2]; R1 += sRed[w2 * 5 + 3]; R2 += sRed[w2 * 5 + 4];
            }
            float bg = 1.f - W;
            out[ray] = D;
            out[nrays + ray * 3 + 0] = R0 + bg;
            out[nrays + ray * 3 + 1] = R1 + bg;
            out[nrays + ray * 3 + 2] = R2 + bg;
        }
    }
}

extern "C" void kernel_launch(void* const* d_in, const int* in_sizes, int n_in,
                              void* d_out, int out_size) {
    const float* rays_o = (const float*)d_in[0];
    const float* rays_d = (const float*)d_in[1];
    const float* W1   = (const float*)d_in[2];
    const float* b1   = (const float*)d_in[3];
    const float* W2   = (const float*)d_in[4];
    const float* b2   = (const float*)d_in[5];
    const float* Wsig = (const float*)d_in[6];
    const float* Wrgb = (const float*)d_in[7];
    const float* brgb = (const float*)d_in[8];
    float* out = (float*)d_out;

    int nrays = in_sizes[0] / 3;   // B*N
    size_t smem_bytes = (size_t)SMEM_FLOATS * sizeof(float);
    cudaFuncSetAttribute(nerf_render_kernel,
                         cudaFuncAttributeMaxDynamicSharedMemorySize, (int)smem_bytes);
    nerf_render_kernel<<<nrays, 128, smem_bytes>>>(rays_o, rays_d, W1, b1, W2, b2,
                                                   Wsig, Wrgb, brgb, out, nrays);
}

// round 3
// speedup vs baseline: 1.8186x; 1.1480x over previous
#include <cuda_runtime.h>
#include <math.h>

#define NS 128
#define NT 256
#define HD 64
#define BOUND 2.0f

// ---- dynamic shared memory layout (float offsets) ----
#define O_W1   0          // 192
#define O_B1   192        // 64
#define O_B2   256        // 64
#define O_WSIG 320        // 64
#define O_WRGB 384        // 201 (+3 pad)
#define O_BRGB 588        // 3 (+1 pad)
#define O_W2   592        // 4096 ([k][j] layout)
#define O_Z    4688       // 256
#define O_SIG  4944       // 256
#define O_RGB  5200       // 768
#define O_HT   5968       // 8192: hT[64][128] / sPart[128][33] / phase buffers
#define SMEM_FLOATS (5968 + 8192)

// phase-B/E buffers live in the HT union (HT is dead during phases B/D/E)
#define O_A    (O_HT + 0)     // 256
#define O_BUF  (O_HT + 256)   // 256
#define O_C    (O_HT + 512)   // 128
#define O_RED  (O_HT + 640)   // 32
#define O_WT   (O_HT + 704)   // 8 (warp totals for scans)

// packed dual-FMA (sm_103a f32x2 path — double-rate fp32)
__device__ __forceinline__ float2 ffma2(float2 a, float2 b, float2 c) {
    float2 d;
    asm("fma.rn.f32x2 %0, %1, %2, %3;"
        : "=l"(reinterpret_cast<unsigned long long&>(d))
        : "l"(reinterpret_cast<unsigned long long&>(a)),
          "l"(reinterpret_cast<unsigned long long&>(b)),
          "l"(reinterpret_cast<unsigned long long&>(c)));
    return d;
}

// NaN-propagating clip (jnp.clip semantics)
__device__ __forceinline__ float clipf(float x, float lo, float hi) {
    return x < lo ? lo : (x > hi ? hi : x);
}

// ---- warp-shuffle scans ----
__device__ __forceinline__ float warp_scan_mul(float v, int lane) {
#pragma unroll
    for (int o = 1; o < 32; o <<= 1) {
        float t = __shfl_up_sync(0xffffffffu, v, o);
        if (lane >= o) v *= t;
    }
    return v;
}
__device__ __forceinline__ float warp_scan_add(float v, int lane) {
#pragma unroll
    for (int o = 1; o < 32; o <<= 1) {
        float t = __shfl_up_sync(0xffffffffu, v, o);
        if (lane >= o) v += t;
    }
    return v;
}
// inclusive product scan over 128 values (one per thread). 1 barrier inside;
// caller must barrier before reusing wt.
__device__ __forceinline__ float scan128_mul(float v, int tid, float* wt) {
    int lane = tid & 31, w = tid >> 5;
    float s = warp_scan_mul(v, lane);
    if (lane == 31) wt[w] = s;
    __syncthreads();
    float pre = 1.f;
#pragma unroll
    for (int k = 0; k < 3; k++) if (k < w) pre *= wt[k];
    return s * pre;
}
__device__ __forceinline__ float scan128_add(float v, int tid, float* wt) {
    int lane = tid & 31, w = tid >> 5;
    float s = warp_scan_add(v, lane);
    if (lane == 31) wt[w] = s;
    __syncthreads();
    float pre = 0.f;
#pragma unroll
    for (int k = 0; k < 3; k++) if (k < w) pre += wt[k];
    return s + pre;
}

// ---------------------------------------------------------------------------
// One field pass for 128 samples. Thread tile mapping chosen so every GEMM
// LDS.128 touches <=128B of unique data (1 wavefront, conflict-free):
//   mt = tid>>3 (4 unique m-groups/warp), nt = tid&7 (8 unique j-groups/warp),
//   j-columns per thread: {nt*4..nt*4+3} U {32+nt*4..32+nt*4+3}.
// ---------------------------------------------------------------------------
__device__ __forceinline__ void field_pass(
    float* sm, int tid, float z,
    float ox, float oy, float oz, float dx, float dy, float dz,
    int outBase)
{
    // ---- layer 1 (3 -> 64), packed, store transposed hT[k][m] ----
    {
        float px = clipf(fmaf(dx, z, ox), -BOUND, BOUND);
        float py = clipf(fmaf(dy, z, oy), -BOUND, BOUND);
        float pz = clipf(fmaf(dz, z, oz), -BOUND, BOUND);
        float2 PX = make_float2(px, px), PY = make_float2(py, py), PZ = make_float2(pz, pz);
        const float2* w1p = (const float2*)(sm + O_W1);
        const float2* b1p = (const float2*)(sm + O_B1);
        float* hT = sm + O_HT;
#pragma unroll
        for (int jp = 0; jp < 32; jp++) {
            float2 v = ffma2(PX, w1p[jp], ffma2(PY, w1p[32 + jp], ffma2(PZ, w1p[64 + jp], b1p[jp])));
            hT[(2 * jp) * 128 + tid]     = fmaxf(v.x, 0.f);
            hT[(2 * jp + 1) * 128 + tid] = fmaxf(v.y, 0.f);
        }
    }
    __syncthreads();

    // ---- GEMM: h2[128][64] = hT^T @ W2, 8(m) x 8(j split 4+4) per thread ----
    const int nt = tid & 7, mt = tid >> 3;
    const int m0 = mt * 8, j0a = nt * 4;          // cols j0a..+3 and 32+j0a..+3
    float2 acc[8][4];
    {
        const float2* b2p = (const float2*)(sm + O_B2);
        float2 bb0 = b2p[j0a / 2],     bb1 = b2p[j0a / 2 + 1];
        float2 bb2 = b2p[16 + j0a / 2], bb3 = b2p[16 + j0a / 2 + 1];
#pragma unroll
        for (int m = 0; m < 8; m++) {
            acc[m][0] = bb0; acc[m][1] = bb1; acc[m][2] = bb2; acc[m][3] = bb3;
        }
        const float* hT = sm + O_HT;
        const float* W2 = sm + O_W2;
#pragma unroll 4
        for (int k = 0; k < 64; k++) {
            float4 a0 = *(const float4*)(hT + k * 128 + m0);
            float4 a1 = *(const float4*)(hT + k * 128 + m0 + 4);
            float4 w0 = *(const float4*)(W2 + k * 64 + j0a);
            float4 w1 = *(const float4*)(W2 + k * 64 + 32 + j0a);
            float2 wp0 = make_float2(w0.x, w0.y), wp1 = make_float2(w0.z, w0.w);
            float2 wp2 = make_float2(w1.x, w1.y), wp3 = make_float2(w1.z, w1.w);
            float am[8] = {a0.x, a0.y, a0.z, a0.w, a1.x, a1.y, a1.z, a1.w};
#pragma unroll
            for (int m = 0; m < 8; m++) {
                float2 hs = make_float2(am[m], am[m]);
                acc[m][0] = ffma2(hs, wp0, acc[m][0]);
                acc[m][1] = ffma2(hs, wp1, acc[m][1]);
                acc[m][2] = ffma2(hs, wp2, acc[m][2]);
                acc[m][3] = ffma2(hs, wp3, acc[m][3]);
            }
        }
    }
    __syncthreads();   // all GEMM reads of hT done before sPart overwrites it

    // ---- relu + head partials for this thread's 8 j-cols -> sPart[m][nt*4+c] ----
    {
        float wsig[8], wr0[8], wr1[8], wr2[8];
#pragma unroll
        for (int c = 0; c < 8; c++) {
            int j = (c < 4) ? (j0a + c) : (32 + j0a + c - 4);
            wsig[c] = sm[O_WSIG + j];
            wr0[c] = sm[O_WRGB + j * 3 + 0];
            wr1[c] = sm[O_WRGB + j * 3 + 1];
            wr2[c] = sm[O_WRGB + j * 3 + 2];
        }
        float* sPart = sm + O_HT;
#pragma unroll
        for (int m = 0; m < 8; m++) {
            float h2v[8];
            h2v[0] = fmaxf(acc[m][0].x, 0.f); h2v[1] = fmaxf(acc[m][0].y, 0.f);
            h2v[2] = fmaxf(acc[m][1].x, 0.f); h2v[3] = fmaxf(acc[m][1].y, 0.f);
            h2v[4] = fmaxf(acc[m][2].x, 0.f); h2v[5] = fmaxf(acc[m][2].y, 0.f);
            h2v[6] = fmaxf(acc[m][3].x, 0.f); h2v[7] = fmaxf(acc[m][3].y, 0.f);
            float sg = 0.f, r0 = 0.f, r1 = 0.f, r2 = 0.f;
#pragma unroll
            for (int c = 0; c < 8; c++) {
                sg = fmaf(h2v[c], wsig[c], sg);
                r0 = fmaf(h2v[c], wr0[c], r0);
                r1 = fmaf(h2v[c], wr1[c], r1);
                r2 = fmaf(h2v[c], wr2[c], r2);
            }
            int base = (m0 + m) * 33 + nt * 4;
            sPart[base + 0] = sg; sPart[base + 1] = r0;
            sPart[base + 2] = r1; sPart[base + 3] = r2;
        }
    }
    __syncthreads();

    // ---- per-sample finalize ----
    {
        const float* sPart = sm + O_HT;
        float sg = 0.f, r0 = 0.f, r1 = 0.f, r2 = 0.f;
#pragma unroll
        for (int g = 0; g < 8; g++) {
            int base = tid * 33 + g * 4;
            sg += sPart[base + 0]; r0 += sPart[base + 1];
            r1 += sPart[base + 2]; r2 += sPart[base + 3];
        }
        r0 += fmaf(dx, sm[O_WRGB + 64 * 3 + 0], fmaf(dy, sm[O_WRGB + 65 * 3 + 0], fmaf(dz, sm[O_WRGB + 66 * 3 + 0], sm[O_BRGB + 0])));
        r1 += fmaf(dx, sm[O_WRGB + 64 * 3 + 1], fmaf(dy, sm[O_WRGB + 65 * 3 + 1], fmaf(dz, sm[O_WRGB + 66 * 3 + 1], sm[O_BRGB + 1])));
        r2 += fmaf(dx, sm[O_WRGB + 64 * 3 + 2], fmaf(dy, sm[O_WRGB + 65 * 3 + 2], fmaf(dz, sm[O_WRGB + 66 * 3 + 2], sm[O_BRGB + 2])));
        float sigma = fmaxf(sg, 0.f) + log1pf(__expf(-fabsf(sg)));   // stable softplus
        sm[O_SIG + outBase + tid] = sigma;
        sm[O_RGB + (outBase + tid) * 3 + 0] = 1.f / (1.f + __expf(-r0));
        sm[O_RGB + (outBase + tid) * 3 + 1] = 1.f / (1.f + __expf(-r1));
        sm[O_RGB + (outBase + tid) * 3 + 2] = 1.f / (1.f + __expf(-r2));
    }
}

// ---------------------------------------------------------------------------
__global__ void __launch_bounds__(128, 4)
nerf_render_kernel(const float* __restrict__ rays_o, const float* __restrict__ rays_d,
                   const float* __restrict__ W1, const float* __restrict__ b1,
                   const float* __restrict__ W2, const float* __restrict__ b2,
                   const float* __restrict__ Wsig, const float* __restrict__ Wrgb,
                   const float* __restrict__ brgb,
                   float* __restrict__ out, int nrays)
{
    extern __shared__ float sm[];
    const int tid = threadIdx.x;
    const int ray = blockIdx.x;

    // ---- cooperative weight load ----
    for (int i = tid; i < 192; i += 128) sm[O_W1 + i] = W1[i];
    if (tid < 64) { sm[O_B1 + tid] = b1[tid]; sm[O_B2 + tid] = b2[tid]; sm[O_WSIG + tid] = Wsig[tid]; }
    for (int i = tid; i < 4096; i += 128) sm[O_W2 + i] = W2[i];
    for (int i = tid; i < 201; i += 128) sm[O_WRGB + i] = Wrgb[i];
    if (tid < 3) sm[O_BRGB + tid] = brgb[tid];

    // ---- per-ray setup ----
    const float ox = rays_o[ray * 3 + 0], oy = rays_o[ray * 3 + 1], oz = rays_o[ray * 3 + 2];
    const float dx = rays_d[ray * 3 + 0], dy = rays_d[ray * 3 + 1], dz = rays_d[ray * 3 + 2];

    float near = -3.0e38f, far = 3.0e38f;
    {
        float o3[3] = {ox, oy, oz}, d3[3] = {dx, dy, dz};
#pragma unroll
        for (int c = 0; c < 3; c++) {
            float den = d3[c] + 1e-15f;
            float tmn = (-BOUND - o3[c]) / den;
            float tmx = ( BOUND - o3[c]) / den;
            near = fmaxf(near, fminf(tmn, tmx));
            far  = fminf(far,  fmaxf(tmn, tmx));
        }
        if (far < near) { near = 1e9f; far = 1e9f; }
        near = fmaxf(near, 0.05f);
    }
    const float span = far - near;
    const float sample_dist = span / (float)NS;

    float* sZ   = sm + O_Z;
    float* sSig = sm + O_SIG;
    float* sRGB = sm + O_RGB;
    float* sA   = sm + O_A;
    float* sBuf = sm + O_BUF;
    float* sC   = sm + O_C;
    float* sRed = sm + O_RED;
    float* sWT  = sm + O_WT;

    __syncthreads();

    // ========== Phase A: coarse ==========
    float zc = near + span * ((float)tid * (1.f / 127.f));
    sZ[tid] = zc;
    field_pass(sm, tid, zc, ox, oy, oz, dx, dy, dz, 0);
    __syncthreads();

    // ========== Phase B: weights -> pdf -> resample ==========
    float new_z;
    {
        float delta = (tid < NS - 1) ? (sZ[tid + 1] - sZ[tid]) : sample_dist;
        float alpha = 1.f - __expf(-delta * sSig[tid]);
        float shifted = 1.f - alpha + 1e-15f;
        if (tid < NS - 1) sC[tid] = sZ[tid] + 0.5f * delta;
        float Tincl = scan128_mul(shifted, tid, sWT);    // barrier inside
        sBuf[tid] = Tincl;
        __syncthreads();
        float w = alpha * (tid == 0 ? 1.f : sBuf[tid - 1]);
        sA[tid] = w;
        __syncthreads();
        float pv = (tid < 126) ? (sA[tid + 1] + 1e-5f) : 0.f;
        float csum = scan128_add(pv, tid, sWT);          // barrier inside
        sBuf[tid] = csum;
        __syncthreads();
        const float invS = 1.f / sBuf[125];

        float u = 0.00390625f + (float)tid * 0.0078125f;
        int lo = 0, hi = 127;
        while (lo < hi) {
            int m = (lo + hi) >> 1;
            float c = (m == 0) ? 0.f : sBuf[m - 1] * invS;
            if (c <= u) lo = m + 1; else hi = m;
        }
        int ind = lo;
        int below = max(ind - 1, 0);
        int above = min(ind, 126);
        float cb = (below == 0) ? 0.f : sBuf[below - 1] * invS;
        float ca = (above == 0) ? 0.f : sBuf[above - 1] * invS;
        float bb = sC[below], ba = sC[above];
        float den = ca - cb;
        if (den < 1e-5f) den = 1.f;
        new_z = bb + ((u - cb) / den) * (ba - bb);
    }
    __syncthreads();

    // ========== Phase C: fine ==========
    sZ[NS + tid] = new_z;
    field_pass(sm, tid, new_z, ox, oy, oz, dx, dy, dz, NS);
    __syncthreads();

    // ========== Phase D: stable merge of two sorted runs ==========
    {
        float zA = sZ[tid], zB = sZ[NS + tid];
        int lo = 0, hi = NS;
        while (lo < hi) { int m = (lo + hi) >> 1; if (sZ[NS + m] < zA) lo = m + 1; else hi = m; }
        int posA = tid + lo;
        lo = 0; hi = NS;
        while (lo < hi) { int m = (lo + hi) >> 1; if (sZ[m] <= zB) lo = m + 1; else hi = m; }
        int posB = tid + lo;

        float sgA = sSig[tid], sgB = sSig[NS + tid];
        float a0 = sRGB[tid * 3 + 0], a1 = sRGB[tid * 3 + 1], a2 = sRGB[tid * 3 + 2];
        float b0 = sRGB[(NS + tid) * 3 + 0], b1v = sRGB[(NS + tid) * 3 + 1], b2v = sRGB[(NS + tid) * 3 + 2];
        __syncthreads();
        sZ[posA] = zA; sSig[posA] = sgA;
        sRGB[posA * 3 + 0] = a0; sRGB[posA * 3 + 1] = a1; sRGB[posA * 3 + 2] = a2;
        sZ[posB] = zB; sSig[posB] = sgB;
        sRGB[posB * 3 + 0] = b0; sRGB[posB * 3 + 1] = b1v; sRGB[posB * 3 + 2] = b2v;
        __syncthreads();
    }

    // ========== Phase E: final composite over 256 sorted samples ==========
    {
        // thread owns consecutive pair i0 = 2*tid, i1 = 2*tid+1
        const int i0 = 2 * tid, i1 = 2 * tid + 1;
        float d0 = sZ[i0 + 1] - sZ[i0];
        float d1 = (i1 < NT - 1) ? (sZ[i1 + 1] - sZ[i1]) : sample_dist;
        float al0 = 1.f - __expf(-d0 * sSig[i0]);
        float al1 = 1.f - __expf(-d1 * sSig[i1]);
        float s0 = 1.f - al0 + 1e-15f;
        float s1 = 1.f - al1 + 1e-15f;

        // pair-based inclusive product scan over 256
        int lane = tid & 31, w = tid >> 5;
        float p = s0 * s1;
        float pincl = warp_scan_mul(p, lane);
        if (lane == 31) sWT[w] = pincl;
        __syncthreads();
        float pre = 1.f;
#pragma unroll
        for (int k = 0; k < 3; k++) if (k < w) pre *= sWT[k];
        float e = __shfl_up_sync(0xffffffffu, pincl, 1);
        e = (lane == 0) ? 1.f : e;
        e *= pre;                      // exclusive product of preceding pairs
        float w0 = al0 * e;            // T_{i0-1} = e
        float w1 = al1 * e * s0;       // T_{i1-1} = e * s0

        float v0 = clipf((sZ[i0] - near) / span, 0.f, 1.f);
        float v1 = clipf((sZ[i1] - near) / span, 0.f, 1.f);
        float wsum = w0 + w1;
        float dsum = w0 * v0 + w1 * v1;
        float rs0 = fmaf(w0, sRGB[i0 * 3 + 0], w1 * sRGB[i1 * 3 + 0]);
        float rs1 = fmaf(w0, sRGB[i0 * 3 + 1], w1 * sRGB[i1 * 3 + 1]);
        float rs2 = fmaf(w0, sRGB[i0 * 3 + 2], w1 * sRGB[i1 * 3 + 2]);

#pragma unroll
        for (int o = 16; o > 0; o >>= 1) {
            wsum += __shfl_down_sync(0xffffffffu, wsum, o);
            dsum += __shfl_down_sync(0xffffffffu, dsum, o);
            rs0  += __shfl_down_sync(0xffffffffu, rs0, o);
            rs1  += __shfl_down_sync(0xffffffffu, rs1, o);
            rs2  += __shfl_down_sync(0xffffffffu, rs2, o);
        }
        if (lane == 0) {
            sRed[w * 5 + 0] = wsum; sRed[w * 5 + 1] = dsum;
            sRed[w * 5 + 2] = rs0;  sRed[w * 5 + 3] = rs1; sRed[w * 5 + 4] = rs2;
        }
        __syncthreads();
        if (tid == 0) {
            float W = 0, D = 0, R0 = 0, R1 = 0, R2 = 0;
#pragma unroll
            for (int w2 = 0; w2 < 4; w2++) {
                W += sRed[w2 * 5 + 0]; D += sRed[w2 * 5 + 1];
                R0 += sRed[w2 * 5 + 2]; R1 += sRed[w2 * 5 + 3]; R2 += sRed[w2 * 5 + 4];
            }
            float bg = 1.f - W;
            out[ray] = D;
            out[nrays + ray * 3 + 0] = R0 + bg;
            out[nrays + ray * 3 + 1] = R1 + bg;
            out[nrays + ray * 3 + 2] = R2 + bg;
        }
    }
}

extern "C" void kernel_launch(void* const* d_in, const int* in_sizes, int n_in,
                              void* d_out, int out_size) {
    const float* rays_o = (const float*)d_in[0];
    const float* rays_d = (const float*)d_in[1];
    const float* W1   = (const float*)d_in[2];
    const float* b1   = (const float*)d_in[3];
    const float* W2   = (const float*)d_in[4];
    const float* b2   = (const float*)d_in[5];
    const float* Wsig = (const float*)d_in[6];
    const float* Wrgb = (const float*)d_in[7];
    const float* brgb = (const float*)d_in[8];
    float* out = (float*)d_out;

    int nrays = in_sizes[0] / 3;   // B*N
    size_t smem_bytes = (size_t)SMEM_FLOATS * sizeof(float);
    cudaFuncSetAttribute(nerf_render_kernel,
                         cudaFuncAttributeMaxDynamicSharedMemorySize, (int)smem_bytes);
    nerf_render_kernel<<<nrays, 128, smem_bytes>>>(rays_o, rays_d, W1, b1, W2, b2,
                                                   Wsig, Wrgb, brgb, out, nrays);
}

// round 5
// speedup vs baseline: 2.7960x; 1.5374x over previous
#include <cuda_runtime.h>
#include <cuda_bf16.h>
#include <math.h>
#include <stdint.h>

#define NS 128
#define NT 256
#define BOUND 2.0f

// ---- dynamic shared memory layout (float indices) ----
#define O_W1    0        // 192
#define O_B1    192      // 64
#define O_WSIG  256      // 64
#define O_WRGB  320      // 201 (+3 pad)
#define O_BRGB  524      // 4
#define O_B2    528      // 64
#define O_Z     592      // 256
#define O_SIG   848      // 256
#define O_RGB   1104     // 768
#define O_RED   1872     // 32
#define O_WT    1904     // 8 (+8 pad)
#define O_AHI   1920     // 4096 floats = 128 rows x 128B bf16 (hi plane)
#define O_ALO   6016     // 4096
#define O_BHI   10112    // 2048 floats = 64 rows x 128B (W2^T hi)
#define O_BLO   12160    // 2048
#define SMEM_FLOATS 14208   // 56832 bytes -> 4 CTAs/SM

// phase-B scratch unioned over A planes (A dead during phases B/D/E)
#define O_BUF   O_AHI          // 256
#define O_C     (O_AHI + 256)  // 128
#define O_A     (O_AHI + 512)  // 256

__device__ __forceinline__ uint32_t smem_u32(const void* p) {
    uint32_t a;
    asm("{ .reg .u64 t; cvta.to.shared.u64 t, %1; cvt.u32.u64 %0, t; }" : "=r"(a) : "l"(p));
    return a;
}

#define LDM_X4(r, addr) \
    asm volatile("ldmatrix.sync.aligned.m8n8.x4.shared.b16 {%0,%1,%2,%3}, [%4];" \
        : "=r"((r)[0]), "=r"((r)[1]), "=r"((r)[2]), "=r"((r)[3]) : "r"(addr))

#define MMA16816(d, a, b0, b1) \
    asm volatile("mma.sync.aligned.m16n8k16.row.col.f32.bf16.bf16.f32 " \
        "{%0,%1,%2,%3}, {%4,%5,%6,%7}, {%8,%9}, {%0,%1,%2,%3};" \
        : "+f"((d)[0]), "+f"((d)[1]), "+f"((d)[2]), "+f"((d)[3]) \
        : "r"((a)[0]), "r"((a)[1]), "r"((a)[2]), "r"((a)[3]), "r"(b0), "r"(b1))

// packed dual-FMA (sm_103a f32x2)
__device__ __forceinline__ float2 ffma2(float2 a, float2 b, float2 c) {
    float2 d;
    asm("fma.rn.f32x2 %0, %1, %2, %3;"
        : "=l"(reinterpret_cast<unsigned long long&>(d))
        : "l"(reinterpret_cast<unsigned long long&>(a)),
          "l"(reinterpret_cast<unsigned long long&>(b)),
          "l"(reinterpret_cast<unsigned long long&>(c)));
    return d;
}
// pack two f32 -> bf16x2 (lo half = x, hi half = y)
__device__ __forceinline__ uint32_t pack_bf16x2(float lo, float hi) {
    uint32_t w;
    asm("cvt.rn.bf16x2.f32 %0, %1, %2;" : "=r"(w) : "f"(hi), "f"(lo));
    return w;
}

__device__ __forceinline__ float clipf(float x, float lo, float hi) {
    return x < lo ? lo : (x > hi ? hi : x);
}

// ---- warp-shuffle scans ----
__device__ __forceinline__ float warp_scan_mul(float v, int lane) {
#pragma unroll
    for (int o = 1; o < 32; o <<= 1) {
        float t = __shfl_up_sync(0xffffffffu, v, o);
        if (lane >= o) v *= t;
    }
    return v;
}
__device__ __forceinline__ float warp_scan_add(float v, int lane) {
#pragma unroll
    for (int o = 1; o < 32; o <<= 1) {
        float t = __shfl_up_sync(0xffffffffu, v, o);
        if (lane >= o) v += t;
    }
    return v;
}
__device__ __forceinline__ float scan128_mul(float v, int tid, float* wt) {
    int lane = tid & 31, w = tid >> 5;
    float s = warp_scan_mul(v, lane);
    if (lane == 31) wt[w] = s;
    __syncthreads();
    float pre = 1.f;
#pragma unroll
    for (int k = 0; k < 3; k++) if (k < w) pre *= wt[k];
    return s * pre;
}
__device__ __forceinline__ float scan128_add(float v, int tid, float* wt) {
    int lane = tid & 31, w = tid >> 5;
    float s = warp_scan_add(v, lane);
    if (lane == 31) wt[w] = s;
    __syncthreads();
    float pre = 0.f;
#pragma unroll
    for (int k = 0; k < 3; k++) if (k < w) pre += wt[k];
    return s + pre;
}

// ---------------------------------------------------------------------------
// One field pass for 128 samples (thread = sample for layer1; warp w owns
// rows 32w..32w+31 for the MMA + epilogue — entirely warp-local, so only
// __syncwarp() is needed inside).
// ---------------------------------------------------------------------------
__device__ __forceinline__ void field_pass(
    float* sm, uint32_t smem_base, int tid, float z,
    float ox, float oy, float oz, float dx, float dy, float dz,
    float dirR0, float dirR1, float dirR2, int outBase)
{
    const int lane = tid & 31;
    const int wid = tid >> 5;

    // ---- layer 1 (3 -> 64) + bf16 hi/lo split into A planes, row = tid ----
    {
        float px = clipf(fmaf(dx, z, ox), -BOUND, BOUND);
        float py = clipf(fmaf(dy, z, oy), -BOUND, BOUND);
        float pz = clipf(fmaf(dz, z, oz), -BOUND, BOUND);
        float2 PX = make_float2(px, px), PY = make_float2(py, py), PZ = make_float2(pz, pz);
        const float2* w1p = (const float2*)(sm + O_W1);
        const float2* b1p = (const float2*)(sm + O_B1);
        const int swx = (tid & 7) << 2;      // 16B-chunk swizzle (in words)
        const int rowbase = tid * 32;        // 32 words per 128B row
#pragma unroll
        for (int q = 0; q < 8; q++) {
            uint32_t whi[4], wlo[4];
#pragma unroll
            for (int t = 0; t < 4; t++) {
                int jp = q * 4 + t;
                float2 v = ffma2(PX, w1p[jp], ffma2(PY, w1p[32 + jp], ffma2(PZ, w1p[64 + jp], b1p[jp])));
                v.x = fmaxf(v.x, 0.f); v.y = fmaxf(v.y, 0.f);
                uint32_t hw = pack_bf16x2(v.x, v.y);
                float fx = __uint_as_float(hw << 16);
                float fy = __uint_as_float(hw & 0xffff0000u);
                uint32_t lw = pack_bf16x2(v.x - fx, v.y - fy);
                whi[t] = hw; wlo[t] = lw;
            }
            int woff = rowbase + ((q * 4) ^ swx);
            *(uint4*)(sm + O_AHI + woff) = make_uint4(whi[0], whi[1], whi[2], whi[3]);
            *(uint4*)(sm + O_ALO + woff) = make_uint4(wlo[0], wlo[1], wlo[2], wlo[3]);
        }
    }
    __syncwarp();   // warp reads only its own 32 rows

    // ---- warp MMA: D[32][64] = Ahi*Bhi + Ahi*Blo + Alo*Bhi ----
    const int m0 = 32 * wid;
    const int ar = m0 + (lane & 15);      // A frag row (m-tile adds +16)
    const int ahl = lane >> 4;            // A k-half
    const int br = (lane & 7) + ((lane >> 4) << 3);  // B row within n16 group
    const int bkh = (lane >> 3) & 1;      // B k-half
    const uint32_t aHiBase = smem_base + O_AHI * 4;
    const uint32_t aLoBase = smem_base + O_ALO * 4;
    const uint32_t bHiBase = smem_base + O_BHI * 4;
    const uint32_t bLoBase = smem_base + O_BLO * 4;

    float d[2][8][4];
#pragma unroll
    for (int mt = 0; mt < 2; mt++)
#pragma unroll
        for (int n = 0; n < 8; n++)
#pragma unroll
            for (int e = 0; e < 4; e++) d[mt][n][e] = 0.f;

#pragma unroll
    for (int ks = 0; ks < 4; ks++) {
        uint32_t ahi[2][4], alo[2][4];
        uint32_t aoff = (uint32_t)(((2 * ks + ahl) ^ (ar & 7)) << 4) + (uint32_t)ar * 128u;
#pragma unroll
        for (int mt = 0; mt < 2; mt++) {
            LDM_X4(ahi[mt], aHiBase + aoff + mt * (16 * 128));
            LDM_X4(alo[mt], aLoBase + aoff + mt * (16 * 128));
        }
#pragma unroll
        for (int np = 0; np < 4; np++) {
            uint32_t bh[4], bl[4];
            uint32_t boff = (uint32_t)(16 * np + br) * 128u +
                            (uint32_t)(((2 * ks + bkh) ^ (br & 7)) << 4);
            LDM_X4(bh, bHiBase + boff);
            LDM_X4(bl, bLoBase + boff);
#pragma unroll
            for (int mt = 0; mt < 2; mt++) {
                MMA16816(d[mt][2 * np + 0], ahi[mt], bh[0], bh[1]);
                MMA16816(d[mt][2 * np + 0], alo[mt], bh[0], bh[1]);
                MMA16816(d[mt][2 * np + 0], ahi[mt], bl[0], bl[1]);
                MMA16816(d[mt][2 * np + 1], ahi[mt], bh[2], bh[3]);
                MMA16816(d[mt][2 * np + 1], alo[mt], bh[2], bh[3]);
                MMA16816(d[mt][2 * np + 1], ahi[mt], bl[2], bl[3]);
            }
        }
    }

    // ---- epilogue: heads on fragments, quad-reduce over t%4 ----
    {
        const int tig = lane & 3, g = lane >> 2;
        float accS[4] = {0, 0, 0, 0}, accR0[4] = {0, 0, 0, 0};
        float accR1[4] = {0, 0, 0, 0}, accR2[4] = {0, 0, 0, 0};
#pragma unroll
        for (int n = 0; n < 8; n++) {
            int j0 = 8 * n + 2 * tig;
            float b2a = sm[O_B2 + j0],     b2b = sm[O_B2 + j0 + 1];
            float wsa = sm[O_WSIG + j0],   wsb = sm[O_WSIG + j0 + 1];
            float wa0 = sm[O_WRGB + 3 * j0 + 0], wb0 = sm[O_WRGB + 3 * j0 + 3];
            float wa1 = sm[O_WRGB + 3 * j0 + 1], wb1 = sm[O_WRGB + 3 * j0 + 4];
            float wa2 = sm[O_WRGB + 3 * j0 + 2], wb2 = sm[O_WRGB + 3 * j0 + 5];
#pragma unroll
            for (int ri = 0; ri < 4; ri++) {
                int mt = ri >> 1, half = ri & 1;
                float h2a = fmaxf(d[mt][n][2 * half + 0] + b2a, 0.f);
                float h2b = fmaxf(d[mt][n][2 * half + 1] + b2b, 0.f);
                accS[ri]  = fmaf(h2a, wsa, fmaf(h2b, wsb, accS[ri]));
                accR0[ri] = fmaf(h2a, wa0, fmaf(h2b, wb0, accR0[ri]));
                accR1[ri] = fmaf(h2a, wa1, fmaf(h2b, wb1, accR1[ri]));
                accR2[ri] = fmaf(h2a, wa2, fmaf(h2b, wb2, accR2[ri]));
            }
        }
#pragma unroll
        for (int ri = 0; ri < 4; ri++) {
#pragma unroll
            for (int o = 1; o <= 2; o <<= 1) {
                accS[ri]  += __shfl_xor_sync(0xffffffffu, accS[ri], o);
                accR0[ri] += __shfl_xor_sync(0xffffffffu, accR0[ri], o);
                accR1[ri] += __shfl_xor_sync(0xffffffffu, accR1[ri], o);
                accR2[ri] += __shfl_xor_sync(0xffffffffu, accR2[ri], o);
            }
        }
        if (tig == 0) {
#pragma unroll
            for (int ri = 0; ri < 4; ri++) {
                int mt = ri >> 1, half = ri & 1;
                int row = m0 + 16 * mt + 8 * half + g;
                float sg = accS[ri];
                float sigma = fmaxf(sg, 0.f) + log1pf(__expf(-fabsf(sg)));
                float r0 = accR0[ri] + dirR0;
                float r1 = accR1[ri] + dirR1;
                float r2 = accR2[ri] + dirR2;
                sm[O_SIG + outBase + row] = sigma;
                sm[O_RGB + (outBase + row) * 3 + 0] = 1.f / (1.f + __expf(-r0));
                sm[O_RGB + (outBase + row) * 3 + 1] = 1.f / (1.f + __expf(-r1));
                sm[O_RGB + (outBase + row) * 3 + 2] = 1.f / (1.f + __expf(-r2));
            }
        }
    }
}

// ---------------------------------------------------------------------------
__global__ void __launch_bounds__(128, 4)
nerf_render_kernel(const float* __restrict__ rays_o, const float* __restrict__ rays_d,
                   const float* __restrict__ W1, const float* __restrict__ b1,
                   const float* __restrict__ W2, const float* __restrict__ b2,
                   const float* __restrict__ Wsig, const float* __restrict__ Wrgb,
                   const float* __restrict__ brgb,
                   float* __restrict__ out, int nrays)
{
    extern __shared__ float sm[];
    const int tid = threadIdx.x;
    const int ray = blockIdx.x;
    const uint32_t smem_base = smem_u32(sm);

    // ---- cooperative weight load ----
    for (int i = tid; i < 192; i += 128) sm[O_W1 + i] = W1[i];
    if (tid < 64) { sm[O_B1 + tid] = b1[tid]; sm[O_B2 + tid] = b2[tid]; sm[O_WSIG + tid] = Wsig[tid]; }
    for (int i = tid; i < 201; i += 128) sm[O_WRGB + i] = Wrgb[i];
    if (tid < 3) sm[O_BRGB + tid] = brgb[tid];

    // W2 split -> B planes: B[j][k] = W2[k][j], 128B rows, chunk-XOR swizzle
    {
        char* bhi = (char*)(sm + O_BHI);
        char* blo = (char*)(sm + O_BLO);
#pragma unroll
        for (int t = 0; t < 32; t++) {
            int i = tid + t * 128;
            int k = i >> 6, j = i & 63;
            float v = W2[i];
            __nv_bfloat16 bh = __float2bfloat16(v);
            float fh = __bfloat162float(bh);
            __nv_bfloat16 bl = __float2bfloat16(v - fh);
            uint32_t byte = (uint32_t)(j * 128 + k * 2);
            uint32_t sw = byte ^ ((byte >> 3) & 0x70);
            *(__nv_bfloat16*)(bhi + sw) = bh;
            *(__nv_bfloat16*)(blo + sw) = bl;
        }
    }

    // ---- per-ray setup ----
    const float ox = rays_o[ray * 3 + 0], oy = rays_o[ray * 3 + 1], oz = rays_o[ray * 3 + 2];
    const float dx = rays_d[ray * 3 + 0], dy = rays_d[ray * 3 + 1], dz = rays_d[ray * 3 + 2];

    float near = -3.0e38f, far = 3.0e38f;
    {
        float o3[3] = {ox, oy, oz}, d3[3] = {dx, dy, dz};
#pragma unroll
        for (int c = 0; c < 3; c++) {
            float den = d3[c] + 1e-15f;
            float tmn = (-BOUND - o3[c]) / den;
            float tmx = ( BOUND - o3[c]) / den;
            near = fmaxf(near, fminf(tmn, tmx));
            far  = fminf(far,  fmaxf(tmn, tmx));
        }
        if (far < near) { near = 1e9f; far = 1e9f; }
        near = fmaxf(near, 0.05f);
    }
    const float span = far - near;
    const float sample_dist = span / (float)NS;

    float* sZ   = sm + O_Z;
    float* sSig = sm + O_SIG;
    float* sRGB = sm + O_RGB;
    float* sBuf = sm + O_BUF;
    float* sC   = sm + O_C;
    float* sA   = sm + O_A;
    float* sRed = sm + O_RED;
    float* sWT  = sm + O_WT;

    __syncthreads();   // weights + B planes visible

    // dir-dependent head terms (same for every sample of this ray)
    const float dirR0 = fmaf(dx, sm[O_WRGB + 64 * 3 + 0], fmaf(dy, sm[O_WRGB + 65 * 3 + 0], fmaf(dz, sm[O_WRGB + 66 * 3 + 0], sm[O_BRGB + 0])));
    const float dirR1 = fmaf(dx, sm[O_WRGB + 64 * 3 + 1], fmaf(dy, sm[O_WRGB + 65 * 3 + 1], fmaf(dz, sm[O_WRGB + 66 * 3 + 1], sm[O_BRGB + 1])));
    const float dirR2 = fmaf(dx, sm[O_WRGB + 64 * 3 + 2], fmaf(dy, sm[O_WRGB + 65 * 3 + 2], fmaf(dz, sm[O_WRGB + 66 * 3 + 2], sm[O_BRGB + 2])));

    // ========== Phase A: coarse ==========
    float zc = near + span * ((float)tid * (1.f / 127.f));
    sZ[tid] = zc;
    field_pass(sm, smem_base, tid, zc, ox, oy, oz, dx, dy, dz, dirR0, dirR1, dirR2, 0);
    __syncthreads();

    // ========== Phase B: weights -> pdf -> resample ==========
    float new_z;
    {
        float delta = (tid < NS - 1) ? (sZ[tid + 1] - sZ[tid]) : sample_dist;
        float alpha = 1.f - __expf(-delta * sSig[tid]);
        float shifted = 1.f - alpha + 1e-15f;
        if (tid < NS - 1) sC[tid] = sZ[tid] + 0.5f * delta;
        float Tincl = scan128_mul(shifted, tid, sWT);
        sBuf[tid] = Tincl;
        __syncthreads();
        float w = alpha * (tid == 0 ? 1.f : sBuf[tid - 1]);
        sA[tid] = w;
        __syncthreads();
        float pv = (tid < 126) ? (sA[tid + 1] + 1e-5f) : 0.f;
        float csum = scan128_add(pv, tid, sWT);
        sBuf[tid] = csum;
        __syncthreads();
        const float invS = 1.f / sBuf[125];

        float u = 0.00390625f + (float)tid * 0.0078125f;
        int lo = 0, hi = 127;
        while (lo < hi) {
            int m = (lo + hi) >> 1;
            float c = (m == 0) ? 0.f : sBuf[m - 1] * invS;
            if (c <= u) lo = m + 1; else hi = m;
        }
        int ind = lo;
        int below = max(ind - 1, 0);
        int above = min(ind, 126);
        float cb = (below == 0) ? 0.f : sBuf[below - 1] * invS;
        float ca = (above == 0) ? 0.f : sBuf[above - 1] * invS;
        float bb = sC[below], ba = sC[above];
        float den = ca - cb;
        if (den < 1e-5f) den = 1.f;
        new_z = bb + ((u - cb) / den) * (ba - bb);
    }
    __syncthreads();

    // ========== Phase C: fine ==========
    sZ[NS + tid] = new_z;
    field_pass(sm, smem_base, tid, new_z, ox, oy, oz, dx, dy, dz, dirR0, dirR1, dirR2, NS);
    __syncthreads();

    // ========== Phase D: stable merge of two sorted runs ==========
    {
        float zA = sZ[tid], zB = sZ[NS + tid];
        int lo = 0, hi = NS;
        while (lo < hi) { int m = (lo + hi) >> 1; if (sZ[NS + m] < zA) lo = m + 1; else hi = m; }
        int posA = tid + lo;
        lo = 0; hi = NS;
        while (lo < hi) { int m = (lo + hi) >> 1; if (sZ[m] <= zB) lo = m + 1; else hi = m; }
        int posB = tid + lo;

        float sgA = sSig[tid], sgB = sSig[NS + tid];
        float a0 = sRGB[tid * 3 + 0], a1 = sRGB[tid * 3 + 1], a2 = sRGB[tid * 3 + 2];
        float b0 = sRGB[(NS + tid) * 3 + 0], b1v = sRGB[(NS + tid) * 3 + 1], b2v = sRGB[(NS + tid) * 3 + 2];
        __syncthreads();
        sZ[posA] = zA; sSig[posA] = sgA;
        sRGB[posA * 3 + 0] = a0; sRGB[posA * 3 + 1] = a1; sRGB[posA * 3 + 2] = a2;
        sZ[posB] = zB; sSig[posB] = sgB;
        sRGB[posB * 3 + 0] = b0; sRGB[posB * 3 + 1] = b1v; sRGB[posB * 3 + 2] = b2v;
        __syncthreads();
    }

    // ========== Phase E: final composite ==========
    {
        const int i0 = 2 * tid, i1 = 2 * tid + 1;
        float d0 = sZ[i0 + 1] - sZ[i0];
        float d1 = (i1 < NT - 1) ? (sZ[i1 + 1] - sZ[i1]) : sample_dist;
        float al0 = 1.f - __expf(-d0 * sSig[i0]);
        float al1 = 1.f - __expf(-d1 * sSig[i1]);
        float s0 = 1.f - al0 + 1e-15f;
        float s1 = 1.f - al1 + 1e-15f;

        int lane = tid & 31, w = tid >> 5;
        float p = s0 * s1;
        float pincl = warp_scan_mul(p, lane);
        if (lane == 31) sWT[w] = pincl;
        __syncthreads();
        float pre = 1.f;
#pragma unroll
        for (int k = 0; k < 3; k++) if (k < w) pre *= sWT[k];
        float e = __shfl_up_sync(0xffffffffu, pincl, 1);
        e = (lane == 0) ? 1.f : e;
        e *= pre;
        float w0 = al0 * e;
        float w1 = al1 * e * s0;

        float v0 = clipf((sZ[i0] - near) / span, 0.f, 1.f);
        float v1 = clipf((sZ[i1] - near) / span, 0.f, 1.f);
        float wsum = w0 + w1;
        float dsum = w0 * v0 + w1 * v1;
        float rs0 = fmaf(w0, sRGB[i0 * 3 + 0], w1 * sRGB[i1 * 3 + 0]);
        float rs1 = fmaf(w0, sRGB[i0 * 3 + 1], w1 * sRGB[i1 * 3 + 1]);
        float rs2 = fmaf(w0, sRGB[i0 * 3 + 2], w1 * sRGB[i1 * 3 + 2]);

#pragma unroll
        for (int o = 16; o > 0; o >>= 1) {
            wsum += __shfl_down_sync(0xffffffffu, wsum, o);
            dsum += __shfl_down_sync(0xffffffffu, dsum, o);
            rs0  += __shfl_down_sync(0xffffffffu, rs0, o);
            rs1  += __shfl_down_sync(0xffffffffu, rs1, o);
            rs2  += __shfl_down_sync(0xffffffffu, rs2, o);
        }
        if (lane == 0) {
            sRed[w * 5 + 0] = wsum; sRed[w * 5 + 1] = dsum;
            sRed[w * 5 + 2] = rs0;  sRed[w * 5 + 3] = rs1; sRed[w * 5 + 4] = rs2;
        }
        __syncthreads();
        if (tid == 0) {
            float W = 0, D = 0, R0 = 0, R1 = 0, R2 = 0;
#pragma unroll
            for (int w2 = 0; w2 < 4; w2++) {
                W += sRed[w2 * 5 + 0]; D += sRed[w2 * 5 + 1];
                R0 += sRed[w2 * 5 + 2]; R1 += sRed[w2 * 5 + 3]; R2 += sRed[w2 * 5 + 4];
            }
            float bg = 1.f - W;
            out[ray] = D;
            out[nrays + ray * 3 + 0] = R0 + bg;
            out[nrays + ray * 3 + 1] = R1 + bg;
            out[nrays + ray * 3 + 2] = R2 + bg;
        }
    }
}

extern "C" void kernel_launch(void* const* d_in, const int* in_sizes, int n_in,
                              void* d_out, int out_size) {
    const float* rays_o = (const float*)d_in[0];
    const float* rays_d = (const float*)d_in[1];
    const float* W1   = (const float*)d_in[2];
    const float* b1   = (const float*)d_in[3];
    const float* W2   = (const float*)d_in[4];
    const float* b2   = (const float*)d_in[5];
    const float* Wsig = (const float*)d_in[6];
    const float* Wrgb = (const float*)d_in[7];
    const float* brgb = (const float*)d_in[8];
    float* out = (float*)d_out;

    int nrays = in_sizes[0] / 3;   // B*N
    size_t smem_bytes = (size_t)SMEM_FLOATS * sizeof(float);
    cudaFuncSetAttribute(nerf_render_kernel,
                         cudaFuncAttributeMaxDynamicSharedMemorySize, (int)smem_bytes);
    nerf_render_kernel<<<nrays, 128, smem_bytes>>>(rays_o, rays_d, W1, b1, W2, b2,
                                                   Wsig, Wrgb, brgb, out, nrays);
}